// round 7
// baseline (speedup 1.0000x reference)
#include <cuda_runtime.h>
#include <math.h>
#include <stdint.h>

// SoftEquivariantLayer v6: warps 0-7 = tf32 HMMA mixing GEMM (unchanged, validated),
// warps 8-15 = per-warp-independent MLP with layer-2 on tf32 HMMA as well.
// All cross-warp MLP barriers removed; w2/w3 SMEM padded for conflict-free access.

#define ROWS    128
#define THREADS 512
#define ZSTRIDE 144            // floats per row (36 float4), k-permuted layout

// ---- SMEM byte offsets ----
#define A_B     0              // Z tile   [128][144] f32  (73728)
#define B_B     73728          // Wb tile  [128][144] f32  (73728)
#define H1_B    147456         // h1 [128][68] f32         (34816)
#define W2P_B   182272         // w2 padded [64][68] f32   (17408)
#define W3T_B   199680         // w3^T [64][8] f32         (2048)
#define W1_B    201728         // [64][8] f32              (2048)
#define B1_B    203776         // 256
#define B2_B    204032         // 256
#define G_B     204288         // 32
#define SC_B    204320         // scales [128][8] f32      (4096)
#define SMEM_BYTES 208416

__device__ float gWb[128 * ZSTRIDE];   // mix_w transposed + k-permuted

// ---------------- helpers ----------------
static __device__ __forceinline__ float gelu_fast(float x) {
    float t = fabsf(x) * 0.7071067811865476f;
    float u = __fdividef(1.0f, fmaf(0.3275911f, t, 1.0f));
    float poly = u * fmaf(u, fmaf(u, fmaf(u, fmaf(u, 1.061405429f, -1.453152027f),
                                          1.421413741f), -0.284496736f), 0.254829592f);
    float e = __expf(-t * t);
    float erfv = fmaf(-poly, e, 1.0f);
    return x * 0.5f * (1.0f + copysignf(erfv, x));
}
static __device__ __forceinline__ float softplus_fast(float x) {
    float e = __expf(-fabsf(x));
    float l = __logf(1.0f + e);
    return x > 0.0f ? x + l : l;
}
static __device__ __forceinline__ void mma8(float4& d, uint32_t a0, uint32_t a1,
                                            uint32_t a2, uint32_t a3,
                                            uint32_t b0, uint32_t b1) {
    asm volatile("mma.sync.aligned.m16n8k8.row.col.f32.tf32.tf32.f32 "
                 "{%0,%1,%2,%3}, {%4,%5,%6,%7}, {%8,%9}, {%0,%1,%2,%3};"
                 : "+f"(d.x), "+f"(d.y), "+f"(d.z), "+f"(d.w)
                 : "r"(a0), "r"(a1), "r"(a2), "r"(a3), "r"(b0), "r"(b1));
}

// ---------------- prep: mix_w -> gWb (transpose + k-permute) ----------------
__global__ void prep_kernel(const float* __restrict__ mixw) {
    int g = blockIdx.x * 256 + threadIdx.x;
    int i = g >> 11, j = (g >> 8) & 7, k = (g >> 4) & 15, d = g & 15;
    int n  = i * 16 + k;
    int kd = j * 16 + d;
    int p  = (kd & 3) * 36 + (kd >> 2);
    gWb[n * ZSTRIDE + p] = mixw[g];
}

// ---------------- main fused kernel ----------------
__global__ void __launch_bounds__(THREADS, 1)
soft_equivariant_kernel(const float* __restrict__ z,
                        const float* __restrict__ w1,
                        const float* __restrict__ b1,
                        const float* __restrict__ w2,
                        const float* __restrict__ b2,
                        const float* __restrict__ w3,
                        const float* __restrict__ gb,
                        float* __restrict__ out)
{
    extern __shared__ char smem[];
    float* Zf  = (float*)(smem + A_B);
    float* Wf  = (float*)(smem + B_B);
    float* h1s = (float*)(smem + H1_B);    // [128][68]
    float* w2p = (float*)(smem + W2P_B);   // [64][68]
    float* w3t = (float*)(smem + W3T_B);   // [64][8]
    float* w1s = (float*)(smem + W1_B);
    float* b1s = (float*)(smem + B1_B);
    float* b2s = (float*)(smem + B2_B);
    float* gts = (float*)(smem + G_B);
    float* scs = (float*)(smem + SC_B);

    const int tid = threadIdx.x;
    const int wid = tid >> 5;
    const int lid = tid & 31;
    const int row0 = blockIdx.x * ROWS;

    // ---- cooperative loads (all 16 warps) ----
    {
        // w2 -> padded stride 68
        const float4* s = (const float4*)w2;
        #pragma unroll
        for (int e = 0; e < 2; ++e) {
            int idx4 = e * THREADS + tid;        // 0..1023
            int o = idx4 >> 4, i4 = idx4 & 15;
            *(float4*)(w2p + o * 68 + i4 * 4) = s[idx4];
        }
        w1s[tid] = w1[tid];
        { int j = tid >> 6, col = tid & 63; w3t[col * 8 + j] = w3[tid]; }
        if (tid < 64) { b1s[tid] = b1[tid]; b2s[tid] = b2[tid]; }
        if (tid < 8)  gts[tid] = 1.0f / (1.0f + __expf(-gb[tid]));
    }
    {
        const float4* s = (const float4*)gWb;
        float4* d4 = (float4*)Wf;
        #pragma unroll
        for (int e = 0; e < 9; ++e) d4[e * THREADS + tid] = s[e * THREADS + tid];
    }
    {
        const float4* zg = (const float4*)(z + (size_t)row0 * 128);
        #pragma unroll
        for (int e = 0; e < 8; ++e) {
            int idx = e * THREADS + tid;
            int row = idx >> 5;
            int w   = idx & 31;
            float4 v = zg[idx];
            float* dst = Zf + row * ZSTRIDE + w;
            dst[0] = v.x; dst[36] = v.y; dst[72] = v.z; dst[108] = v.w;
        }
    }
    __syncthreads();

    if (wid < 8) {
        // ================= GEMM warps (unchanged from v5) =================
        const int mw = wid & 3;
        const int nh = wid >> 2;
        const int qt = lid >> 2;
        const int qc = lid & 3;

        float4 acc[2][8];
        #pragma unroll
        for (int mt = 0; mt < 2; ++mt)
            #pragma unroll
            for (int nt = 0; nt < 8; ++nt) acc[mt][nt] = make_float4(0.f, 0.f, 0.f, 0.f);

        const float4* Z4 = (const float4*)Zf;
        const float4* W4 = (const float4*)Wf;
        #pragma unroll
        for (int ch = 0; ch < 8; ++ch) {
            float4 Af[4];
            #pragma unroll
            for (int mt = 0; mt < 2; ++mt)
                #pragma unroll
                for (int rh = 0; rh < 2; ++rh) {
                    int r = mw * 32 + mt * 16 + rh * 8 + qt;
                    Af[mt * 2 + rh] = Z4[r * 36 + qc * 9 + ch];
                }
            #pragma unroll
            for (int half = 0; half < 2; ++half) {
                float4 Bf[4];
                #pragma unroll
                for (int t = 0; t < 4; ++t) {
                    int n = nh * 64 + (half * 4 + t) * 8 + qt;
                    Bf[t] = W4[n * 36 + qc * 9 + ch];
                }
                #pragma unroll
                for (int mt = 0; mt < 2; ++mt) {
                    uint32_t a0 = __float_as_uint(Af[2 * mt].x);
                    uint32_t a1 = __float_as_uint(Af[2 * mt + 1].x);
                    uint32_t a2 = __float_as_uint(Af[2 * mt].y);
                    uint32_t a3 = __float_as_uint(Af[2 * mt + 1].y);
                    uint32_t c0 = __float_as_uint(Af[2 * mt].z);
                    uint32_t c1 = __float_as_uint(Af[2 * mt + 1].z);
                    uint32_t c2 = __float_as_uint(Af[2 * mt].w);
                    uint32_t c3 = __float_as_uint(Af[2 * mt + 1].w);
                    #pragma unroll
                    for (int t = 0; t < 4; ++t) {
                        mma8(acc[mt][half * 4 + t], a0, a1, a2, a3,
                             __float_as_uint(Bf[t].x), __float_as_uint(Bf[t].y));
                        mma8(acc[mt][half * 4 + t], c0, c1, c2, c3,
                             __float_as_uint(Bf[t].z), __float_as_uint(Bf[t].w));
                    }
                }
            }
        }
        __syncthreads();     // wait for MLP warps' scales

        #pragma unroll
        for (int mt = 0; mt < 2; ++mt) {
            #pragma unroll
            for (int nt = 0; nt < 8; ++nt) {
                const int bundle = nh * 4 + (nt >> 1);
                const float g = gts[bundle];
                const int x0 = nh * 64 + nt * 8 + 2 * qc;
                const int p0 = (x0 & 3) * 36 + (x0 >> 2);
                const int p1 = ((x0 + 1) & 3) * 36 + ((x0 + 1) >> 2);
                #pragma unroll
                for (int rh = 0; rh < 2; ++rh) {
                    const int r = mw * 32 + mt * 16 + rh * 8 + qt;
                    const float s1 = 1.0f + scs[r * 8 + bundle];
                    float z0 = Zf[r * ZSTRIDE + p0];
                    float z1 = Zf[r * ZSTRIDE + p1];
                    float m0 = (rh == 0) ? acc[mt][nt].x : acc[mt][nt].z;
                    float m1 = (rh == 0) ? acc[mt][nt].y : acc[mt][nt].w;
                    float2 o = make_float2(z0 * s1 + g * m0, z1 * s1 + g * m1);
                    *(float2*)(out + (size_t)(row0 + r) * 128 + x0) = o;
                }
            }
        }
    } else {
        // ================= MLP warps: each owns 16 rows, fully independent ======
        const int u = wid - 8;             // 0..7
        const int r0 = u * 16;             // first row of this warp
        const int lrow = lid & 15;         // local row
        const int half = lid >> 4;         // 0/1 split
        const int row = r0 + lrow;

        // ---- norms: lane covers c in {2*half, 2*half+1}; partner via shfl_xor(16)
        float pn[8];
        #pragma unroll
        for (int q = 0; q < 8; ++q) pn[q] = 0.0f;
        {
            const float4* Z4 = (const float4*)Zf;
            #pragma unroll
            for (int cc = 0; cc < 2; ++cc) {
                int c = 2 * half + cc;
                #pragma unroll
                for (int q = 0; q < 8; ++q) {
                    float4 v = Z4[row * 36 + c * 9 + q];
                    pn[q] += v.x * v.x + v.y * v.y + v.z * v.z + v.w * v.w;
                }
            }
        }
        float nrm[8];
        #pragma unroll
        for (int q = 0; q < 8; ++q) {
            float o = __shfl_xor_sync(0xffffffffu, pn[q], 16);
            nrm[q] = sqrtf(pn[q] + o) + 1e-8f;
        }

        // ---- layer 1: lane computes 32 outputs (half-split), stores to h1s ----
        {
            float* hrow = h1s + row * 68 + half * 32;
            #pragma unroll
            for (int p = 0; p < 8; ++p) {
                float4 r4;
                float* rr = (float*)&r4;
                #pragma unroll
                for (int s = 0; s < 4; ++s) {
                    int o = half * 32 + 4 * p + s;
                    float a = b1s[o];
                    const float4* wr = (const float4*)(w1s + o * 8);
                    float4 wa = wr[0], wb = wr[1];
                    a += nrm[0] * wa.x + nrm[1] * wa.y + nrm[2] * wa.z + nrm[3] * wa.w;
                    a += nrm[4] * wb.x + nrm[5] * wb.y + nrm[6] * wb.z + nrm[7] * wb.w;
                    rr[s] = gelu_fast(a);
                }
                *(float4*)(hrow + 4 * p) = r4;
            }
        }
        __syncwarp();

        // ---- layer 2: tf32 mma, A = h1s[16 rows x 64], B = w2 (n=64) ----
        const int qt = lid >> 2;
        const int qc = lid & 3;
        float4 acc[8];
        #pragma unroll
        for (int nt = 0; nt < 8; ++nt) acc[nt] = make_float4(0.f, 0.f, 0.f, 0.f);

        #pragma unroll
        for (int ch = 0; ch < 8; ++ch) {
            int kk = ch * 8;
            uint32_t a0 = __float_as_uint(h1s[(r0 + qt) * 68 + kk + qc]);
            uint32_t a1 = __float_as_uint(h1s[(r0 + qt + 8) * 68 + kk + qc]);
            uint32_t a2 = __float_as_uint(h1s[(r0 + qt) * 68 + kk + qc + 4]);
            uint32_t a3 = __float_as_uint(h1s[(r0 + qt + 8) * 68 + kk + qc + 4]);
            #pragma unroll
            for (int nt = 0; nt < 8; ++nt) {
                uint32_t b0 = __float_as_uint(w2p[(nt * 8 + qt) * 68 + kk + qc]);
                uint32_t b1v = __float_as_uint(w2p[(nt * 8 + qt) * 68 + kk + qc + 4]);
                mma8(acc[nt], a0, a1, a2, a3, b0, b1v);
            }
        }

        // ---- bias + gelu on fragments; layer 3 partials; quad reduce ----
        float s0[8], s1[8];
        #pragma unroll
        for (int j = 0; j < 8; ++j) { s0[j] = 0.0f; s1[j] = 0.0f; }
        #pragma unroll
        for (int nt = 0; nt < 8; ++nt) {
            int c0 = nt * 8 + 2 * qc;
            float bb0 = b2s[c0], bb1 = b2s[c0 + 1];
            float h00 = gelu_fast(acc[nt].x + bb0);   // row qt,   col c0
            float h01 = gelu_fast(acc[nt].y + bb1);   // row qt,   col c0+1
            float h10 = gelu_fast(acc[nt].z + bb0);   // row qt+8, col c0
            float h11 = gelu_fast(acc[nt].w + bb1);   // row qt+8, col c0+1
            const float4* wa = (const float4*)(w3t + c0 * 8);        // [c0][0..7]
            const float4* wb = (const float4*)(w3t + (c0 + 1) * 8);  // [c0+1][0..7]
            float4 wa0 = wa[0], wa1 = wa[1], wb0 = wb[0], wb1 = wb[1];
            s0[0] += h00 * wa0.x + h01 * wb0.x;  s0[1] += h00 * wa0.y + h01 * wb0.y;
            s0[2] += h00 * wa0.z + h01 * wb0.z;  s0[3] += h00 * wa0.w + h01 * wb0.w;
            s0[4] += h00 * wa1.x + h01 * wb1.x;  s0[5] += h00 * wa1.y + h01 * wb1.y;
            s0[6] += h00 * wa1.z + h01 * wb1.z;  s0[7] += h00 * wa1.w + h01 * wb1.w;
            s1[0] += h10 * wa0.x + h11 * wb0.x;  s1[1] += h10 * wa0.y + h11 * wb0.y;
            s1[2] += h10 * wa0.z + h11 * wb0.z;  s1[3] += h10 * wa0.w + h11 * wb0.w;
            s1[4] += h10 * wa1.x + h11 * wb1.x;  s1[5] += h10 * wa1.y + h11 * wb1.y;
            s1[6] += h10 * wa1.z + h11 * wb1.z;  s1[7] += h10 * wa1.w + h11 * wb1.w;
        }
        #pragma unroll
        for (int j = 0; j < 8; ++j) {
            s0[j] += __shfl_xor_sync(0xffffffffu, s0[j], 1);
            s0[j] += __shfl_xor_sync(0xffffffffu, s0[j], 2);
            s1[j] += __shfl_xor_sync(0xffffffffu, s1[j], 1);
            s1[j] += __shfl_xor_sync(0xffffffffu, s1[j], 2);
        }
        if (qc == 0) {
            float* d0 = scs + (r0 + qt) * 8;
            float* d1 = scs + (r0 + qt + 8) * 8;
            *(float4*)(d0)     = make_float4(softplus_fast(s0[0]), softplus_fast(s0[1]),
                                             softplus_fast(s0[2]), softplus_fast(s0[3]));
            *(float4*)(d0 + 4) = make_float4(softplus_fast(s0[4]), softplus_fast(s0[5]),
                                             softplus_fast(s0[6]), softplus_fast(s0[7]));
            *(float4*)(d1)     = make_float4(softplus_fast(s1[0]), softplus_fast(s1[1]),
                                             softplus_fast(s1[2]), softplus_fast(s1[3]));
            *(float4*)(d1 + 4) = make_float4(softplus_fast(s1[4]), softplus_fast(s1[5]),
                                             softplus_fast(s1[6]), softplus_fast(s1[7]));
        }
        __syncthreads();     // release GEMM warps into epilogue
    }
}

extern "C" void kernel_launch(void* const* d_in, const int* in_sizes, int n_in,
                              void* d_out, int out_size)
{
    const float* z    = (const float*)d_in[0];
    const float* w1   = (const float*)d_in[1];
    const float* b1   = (const float*)d_in[2];
    const float* w2   = (const float*)d_in[3];
    const float* b2   = (const float*)d_in[4];
    const float* w3   = (const float*)d_in[5];
    const float* mixw = (const float*)d_in[6];
    const float* gb   = (const float*)d_in[7];
    float* out = (float*)d_out;

    int Btot = in_sizes[0] / 128;            // 524288 rows
    int nblocks = Btot / ROWS;               // 4096

    prep_kernel<<<64, 256>>>(mixw);

    static bool attr_set = false;
    if (!attr_set) {
        cudaFuncSetAttribute(soft_equivariant_kernel,
                             cudaFuncAttributeMaxDynamicSharedMemorySize, SMEM_BYTES);
        attr_set = true;
    }
    soft_equivariant_kernel<<<nblocks, THREADS, SMEM_BYTES>>>(
        z, w1, b1, w2, b2, w3, gb, out);
}

// round 8
// speedup vs baseline: 1.3581x; 1.3581x over previous
#include <cuda_runtime.h>
#include <cuda_bf16.h>
#include <math.h>
#include <stdint.h>

// SoftEquivariantLayer v7: v5 skeleton (measured best) + mixing GEMM moved to
// bf16 mma.m16n8k16. A fragments via ldmatrix.x4 from bf16 Z copy; B pre-packed
// in per-lane fragment order by the prep kernel (conflict-free LDS.128).
// MLP warps identical to v5 (measured 470us) with row-major Zf indexing.

#define ROWS    128
#define THREADS 512

// ---- SMEM byte offsets ----
#define ZF_B    0          // Z fp32 [128][132] row-major       (67584)
#define ZH_B    67584      // Z bf16 [128] rows, 272B stride    (34816)
#define WH_B    102400     // packed B frags bf16               (32768)
#define H1_B    135168     // u64 [128][33]                     (33792)
#define NP_B    168960     // f32 [2][128][8]                   (8192)
#define SC_B    177152     // f32 [128][8]                      (4096)
#define W2_B    181248     // f32 [64][64]                      (16384)
#define W1_B    197632     // f32 [64][8]                       (2048)
#define W3_B    199680     // f32 [8][64]                       (2048)
#define B1_B    201728     // 256
#define B2_B    201984     // 256
#define G_B     202240     // 32
#define SMEM_BYTES 202272

__device__ __nv_bfloat16 gWpk[16384];   // mix_w: bf16, fragment-packed

// ---------------- helpers ----------------
static __device__ __forceinline__ uint32_t s2u(const void* p) {
    uint32_t a;
    asm("{ .reg .u64 t; cvta.to.shared.u64 t, %1; cvt.u32.u64 %0, t; }" : "=r"(a) : "l"(p));
    return a;
}
static __device__ __forceinline__ unsigned long long pack2(float lo, float hi) {
    unsigned long long r; asm("mov.b64 %0, {%1,%2};" : "=l"(r) : "f"(lo), "f"(hi)); return r;
}
static __device__ __forceinline__ void fma2(unsigned long long& d, unsigned long long a, unsigned long long b) {
    asm("fma.rn.f32x2 %0, %1, %2, %0;" : "+l"(d) : "l"(a), "l"(b));
}
static __device__ __forceinline__ float2 unpack2(unsigned long long v) {
    float2 f; asm("mov.b64 {%0,%1}, %2;" : "=f"(f.x), "=f"(f.y) : "l"(v)); return f;
}
static __device__ __forceinline__ float gelu_fast(float x) {
    float t = fabsf(x) * 0.7071067811865476f;
    float u = __fdividef(1.0f, fmaf(0.3275911f, t, 1.0f));
    float poly = u * fmaf(u, fmaf(u, fmaf(u, fmaf(u, 1.061405429f, -1.453152027f),
                                          1.421413741f), -0.284496736f), 0.254829592f);
    float e = __expf(-t * t);
    float erfv = fmaf(-poly, e, 1.0f);
    return x * 0.5f * (1.0f + copysignf(erfv, x));
}
static __device__ __forceinline__ float softplus_fast(float x) {
    float e = __expf(-fabsf(x));
    float l = __logf(1.0f + e);
    return x > 0.0f ? x + l : l;
}
static __device__ __forceinline__ void mma16(float4& d, uint32_t a0, uint32_t a1,
                                             uint32_t a2, uint32_t a3,
                                             uint32_t b0, uint32_t b1) {
    asm volatile("mma.sync.aligned.m16n8k16.row.col.f32.bf16.bf16.f32 "
                 "{%0,%1,%2,%3}, {%4,%5,%6,%7}, {%8,%9}, {%0,%1,%2,%3};"
                 : "+f"(d.x), "+f"(d.y), "+f"(d.z), "+f"(d.w)
                 : "r"(a0), "r"(a1), "r"(a2), "r"(a3), "r"(b0), "r"(b1));
}
static __device__ __forceinline__ void ldsm4(uint32_t& r0, uint32_t& r1,
                                             uint32_t& r2, uint32_t& r3, uint32_t addr) {
    asm volatile("ldmatrix.sync.aligned.m8n8.x4.shared.b16 {%0,%1,%2,%3}, [%4];"
                 : "=r"(r0), "=r"(r1), "=r"(r2), "=r"(r3) : "r"(addr));
}
static __device__ __forceinline__ void barrier_mlp() {
    asm volatile("bar.sync 1, 256;" ::: "memory");
}

// ---------------- prep: mix_w -> gWpk (bf16, fragment-packed) ----------------
// Element (n = i*16+k_, kd = j*16+d). Packed so each GEMM warp's B loads are
// 4 conflict-free LDS.128 per k-step: layout [nh][ks][frag i][lid][pp][b][h].
__global__ void prep_kernel(const float* __restrict__ mixw) {
    int g = blockIdx.x * 256 + threadIdx.x;
    int i = g >> 11, j = (g >> 8) & 7, k = (g >> 4) & 15, d = g & 15;
    int n  = i * 16 + k;
    int kd = j * 16 + d;
    int nh = n >> 6, nt = (n >> 3) & 7, qt = n & 7;
    int ks = kd >> 4, kr = kd & 15;
    int b  = kr >> 3, qc = (kr & 7) >> 1, h = kr & 1;
    int lid = qt * 4 + qc;
    int idx = nh * 8192 + ks * 1024 + (nt >> 1) * 256 + lid * 8 + (nt & 1) * 4 + b * 2 + h;
    gWpk[idx] = __float2bfloat16(mixw[g]);
}

// ---------------- main fused kernel ----------------
__global__ void __launch_bounds__(THREADS, 1)
soft_equivariant_kernel(const float* __restrict__ z,
                        const float* __restrict__ w1,
                        const float* __restrict__ b1,
                        const float* __restrict__ w2,
                        const float* __restrict__ b2,
                        const float* __restrict__ w3,
                        const float* __restrict__ gb,
                        float* __restrict__ out)
{
    extern __shared__ char smem[];
    float* Zf  = (float*)(smem + ZF_B);
    unsigned long long* h1u = (unsigned long long*)(smem + H1_B);
    float* np  = (float*)(smem + NP_B);
    float* scs = (float*)(smem + SC_B);
    float* w2s = (float*)(smem + W2_B);
    float* w1s = (float*)(smem + W1_B);
    float* w3s = (float*)(smem + W3_B);
    float* b1s = (float*)(smem + B1_B);
    float* b2s = (float*)(smem + B2_B);
    float* gts = (float*)(smem + G_B);

    const int tid = threadIdx.x;
    const int wid = tid >> 5;
    const int lid = tid & 31;
    const int row0 = blockIdx.x * ROWS;
    const uint32_t smb = s2u(smem);

    // ---- cooperative loads ----
    {
        const float4* s = (const float4*)w2;
        float4* d4 = (float4*)w2s;
        d4[tid] = s[tid]; d4[tid + 512] = s[tid + 512];
        w1s[tid] = w1[tid];
        w3s[tid] = w3[tid];
        if (tid < 64) { b1s[tid] = b1[tid]; b2s[tid] = b2[tid]; }
        if (tid < 8)  gts[tid] = 1.0f / (1.0f + __expf(-gb[tid]));
    }
    {   // packed B: 32KB linear copy
        const float4* s = (const float4*)gWpk;
        float4* d4 = (float4*)(smem + WH_B);
        #pragma unroll
        for (int e = 0; e < 4; ++e) d4[e * THREADS + tid] = s[e * THREADS + tid];
    }
    {   // z: fp32 row-major + bf16 copy (272B stride)
        const float4* zg = (const float4*)(z + (size_t)row0 * 128);
        #pragma unroll
        for (int e = 0; e < 8; ++e) {
            int idx = e * THREADS + tid;
            int row = idx >> 5;
            int c4  = idx & 31;
            float4 v = zg[idx];
            *(float4*)(Zf + row * 132 + c4 * 4) = v;
            __nv_bfloat162 p0 = __floats2bfloat162_rn(v.x, v.y);
            __nv_bfloat162 p1 = __floats2bfloat162_rn(v.z, v.w);
            uint32_t u0 = *(uint32_t*)&p0, u1 = *(uint32_t*)&p1;
            uint2 pr = make_uint2(u0, u1);
            *(uint2*)(smem + ZH_B + row * 272 + c4 * 8) = pr;
        }
    }
    __syncthreads();

    if (wid < 8) {
        // ================= GEMM warps: bf16 m16n8k16, 32x64 tile each =========
        const int mw = wid & 3;        // rows mw*32..
        const int nh = wid >> 2;       // cols nh*64..
        const int qt = lid >> 2;
        const int qc = lid & 3;

        float4 acc[2][8];
        #pragma unroll
        for (int mt = 0; mt < 2; ++mt)
            #pragma unroll
            for (int nt = 0; nt < 8; ++nt) acc[mt][nt] = make_float4(0.f, 0.f, 0.f, 0.f);

        // ldmatrix lane address components
        const int lm_row = ((lid >> 3) & 1) * 8 + (lid & 7);   // row within 16-tile
        const int lm_col = (lid >> 4) * 16;                    // byte col offset
        const uint32_t abase = smb + ZH_B + (mw * 32 + lm_row) * 272 + lm_col;
        const char* wbase = smem + WH_B + nh * 16384;

        #pragma unroll
        for (int ks = 0; ks < 8; ++ks) {
            uint32_t a[2][4];
            #pragma unroll
            for (int mt = 0; mt < 2; ++mt)
                ldsm4(a[mt][0], a[mt][1], a[mt][2], a[mt][3],
                      abase + mt * 16 * 272 + ks * 32);
            const char* wp = wbase + ks * 2048 + lid * 16;
            uint4 l0 = *(const uint4*)(wp);
            uint4 l1 = *(const uint4*)(wp + 512);
            uint4 l2 = *(const uint4*)(wp + 1024);
            uint4 l3 = *(const uint4*)(wp + 1536);
            #pragma unroll
            for (int mt = 0; mt < 2; ++mt) {
                mma16(acc[mt][0], a[mt][0], a[mt][1], a[mt][2], a[mt][3], l0.x, l0.y);
                mma16(acc[mt][1], a[mt][0], a[mt][1], a[mt][2], a[mt][3], l0.z, l0.w);
                mma16(acc[mt][2], a[mt][0], a[mt][1], a[mt][2], a[mt][3], l1.x, l1.y);
                mma16(acc[mt][3], a[mt][0], a[mt][1], a[mt][2], a[mt][3], l1.z, l1.w);
                mma16(acc[mt][4], a[mt][0], a[mt][1], a[mt][2], a[mt][3], l2.x, l2.y);
                mma16(acc[mt][5], a[mt][0], a[mt][1], a[mt][2], a[mt][3], l2.z, l2.w);
                mma16(acc[mt][6], a[mt][0], a[mt][1], a[mt][2], a[mt][3], l3.x, l3.y);
                mma16(acc[mt][7], a[mt][0], a[mt][1], a[mt][2], a[mt][3], l3.z, l3.w);
            }
        }
        __syncthreads();     // wait for MLP warps' scales

        // ---- epilogue ----
        #pragma unroll
        for (int mt = 0; mt < 2; ++mt) {
            #pragma unroll
            for (int nt = 0; nt < 8; ++nt) {
                const int bundle = nh * 4 + (nt >> 1);
                const float g = gts[bundle];
                const int x0 = nh * 64 + nt * 8 + 2 * qc;
                #pragma unroll
                for (int rh = 0; rh < 2; ++rh) {
                    const int r = mw * 32 + mt * 16 + rh * 8 + qt;
                    const float s1 = 1.0f + scs[r * 8 + bundle];
                    float2 zv = *(const float2*)(Zf + r * 132 + x0);
                    float m0 = (rh == 0) ? acc[mt][nt].x : acc[mt][nt].z;
                    float m1 = (rh == 0) ? acc[mt][nt].y : acc[mt][nt].w;
                    float2 o = make_float2(zv.x * s1 + g * m0, zv.y * s1 + g * m1);
                    *(float2*)(out + (size_t)(row0 + r) * 128 + x0) = o;
                }
            }
        }
    } else {
        // ================= MLP warps (v5, row-major Zf indexing) ==============
        const int u = wid - 8;
        const int rgrp = u >> 1;
        const int h = u & 1;
        const int row = rgrp * 32 + lid;
        const float4* Z4 = (const float4*)Zf;    // stride 33 float4 per row

        // ---- norms (half of each bundle's k, then exchange) ----
        float pn[8];
        #pragma unroll
        for (int j = 0; j < 8; ++j) pn[j] = 0.0f;
        #pragma unroll
        for (int cc = 0; cc < 2; ++cc) {
            #pragma unroll
            for (int j = 0; j < 8; ++j) {
                float4 v = Z4[row * 33 + j * 4 + 2 * h + cc];
                pn[j] += v.x * v.x + v.y * v.y + v.z * v.z + v.w * v.w;
            }
        }
        {
            float4* d4 = (float4*)(np + (h * 128 + row) * 8);
            d4[0] = make_float4(pn[0], pn[1], pn[2], pn[3]);
            d4[1] = make_float4(pn[4], pn[5], pn[6], pn[7]);
        }
        barrier_mlp();
        float nrm[8];
        {
            const float4* o4 = (const float4*)(np + ((1 - h) * 128 + row) * 8);
            float4 a = o4[0], b = o4[1];
            nrm[0] = sqrtf(pn[0] + a.x) + 1e-8f; nrm[1] = sqrtf(pn[1] + a.y) + 1e-8f;
            nrm[2] = sqrtf(pn[2] + a.z) + 1e-8f; nrm[3] = sqrtf(pn[3] + a.w) + 1e-8f;
            nrm[4] = sqrtf(pn[4] + b.x) + 1e-8f; nrm[5] = sqrtf(pn[5] + b.y) + 1e-8f;
            nrm[6] = sqrtf(pn[6] + b.z) + 1e-8f; nrm[7] = sqrtf(pn[7] + b.w) + 1e-8f;
        }

        // ---- layer 1 (half: 32 outputs = 16 pairs) ----
        #pragma unroll
        for (int p = 0; p < 16; ++p) {
            int o0 = h * 32 + 2 * p;
            float a0 = b1s[o0], a1 = b1s[o0 + 1];
            #pragma unroll
            for (int j = 0; j < 8; ++j) {
                a0 += nrm[j] * w1s[o0 * 8 + j];
                a1 += nrm[j] * w1s[(o0 + 1) * 8 + j];
            }
            h1u[row * 33 + h * 16 + p] = pack2(gelu_fast(a0), gelu_fast(a1));
        }
        barrier_mlp();

        unsigned long long hp[32];
        #pragma unroll
        for (int p = 0; p < 32; ++p) hp[p] = h1u[row * 33 + p];

        // ---- layer 2 (half: 32 outputs) fused with layer 3 partials ----
        float sacc[8];
        #pragma unroll
        for (int j = 0; j < 8; ++j) sacc[j] = 0.0f;
        #pragma unroll 2
        for (int oo = 0; oo < 32; ++oo) {
            int o = h * 32 + oo;
            unsigned long long pa = 0ull, pb = 0ull;
            const ulonglong2* wr = (const ulonglong2*)(w2s + o * 64);
            #pragma unroll
            for (int ii = 0; ii < 16; ++ii) {
                ulonglong2 q = wr[ii];
                fma2(pa, hp[2 * ii], q.x);
                fma2(pb, hp[2 * ii + 1], q.y);
            }
            float2 fa = unpack2(pa), fb = unpack2(pb);
            float h2o = gelu_fast(b2s[o] + (fa.x + fa.y) + (fb.x + fb.y));
            #pragma unroll
            for (int j = 0; j < 8; ++j) sacc[j] += h2o * w3s[j * 64 + o];
        }
        {
            float4* d4 = (float4*)(np + (h * 128 + row) * 8);
            d4[0] = make_float4(sacc[0], sacc[1], sacc[2], sacc[3]);
            d4[1] = make_float4(sacc[4], sacc[5], sacc[6], sacc[7]);
        }
        barrier_mlp();

        // ---- reduce + softplus (each h-half stores 4 of 8 scales) ----
        {
            const float4* p0 = (const float4*)(np + row * 8) + h;
            const float4* p1 = (const float4*)(np + (128 + row) * 8) + h;
            float4 a = p0[0], b = p1[0];
            float4 r;
            r.x = softplus_fast(a.x + b.x);
            r.y = softplus_fast(a.y + b.y);
            r.z = softplus_fast(a.z + b.z);
            r.w = softplus_fast(a.w + b.w);
            ((float4*)(scs + row * 8))[h] = r;
        }
        __syncthreads();     // release GEMM warps into epilogue
    }
}

extern "C" void kernel_launch(void* const* d_in, const int* in_sizes, int n_in,
                              void* d_out, int out_size)
{
    const float* z    = (const float*)d_in[0];
    const float* w1   = (const float*)d_in[1];
    const float* b1   = (const float*)d_in[2];
    const float* w2   = (const float*)d_in[3];
    const float* b2   = (const float*)d_in[4];
    const float* w3   = (const float*)d_in[5];
    const float* mixw = (const float*)d_in[6];
    const float* gb   = (const float*)d_in[7];
    float* out = (float*)d_out;

    int Btot = in_sizes[0] / 128;            // 524288 rows
    int nblocks = Btot / ROWS;               // 4096

    prep_kernel<<<64, 256>>>(mixw);

    static bool attr_set = false;
    if (!attr_set) {
        cudaFuncSetAttribute(soft_equivariant_kernel,
                             cudaFuncAttributeMaxDynamicSharedMemorySize, SMEM_BYTES);
        attr_set = true;
    }
    soft_equivariant_kernel<<<nblocks, THREADS, SMEM_BYTES>>>(
        z, w1, b1, w2, b2, w3, gb, out);
}

// round 9
// speedup vs baseline: 1.9363x; 1.4257x over previous
#include <cuda_runtime.h>
#include <cuda_bf16.h>
#include <cuda_fp16.h>
#include <math.h>
#include <stdint.h>

// SoftEquivariantLayer v8: v7 mixing GEMM (bf16 m16n8k16 + LDSM + packed B,
// measured 389us) + MLP layer-2 moved to fp16 m16n8k16 with the same
// LDSM/fragment-packed-weight recipe. MLP warps fully warp-independent.

#define ROWS    128
#define THREADS 512

// ---- SMEM byte offsets ----
#define ZF_B    0          // Z fp32 [128][132] row-major       (67584)
#define ZH_B    67584      // Z bf16 [128] rows, 272B stride    (34816)
#define WH_B    102400     // packed mixing B frags bf16        (32768)
#define H1H_B   135168     // h1 fp16 [128] rows, 144B stride   (18432)
#define W2H_B   153600     // packed w2 frags fp16              (8192)
#define W3T_B   161792     // w3^T [64][8] f32                  (2048)
#define W1_B    163840     // [64][8] f32                       (2048)
#define B1_B    165888     // 256
#define B2_B    166144     // 256
#define G_B     166400     // 32
#define SC_B    166432     // scales [128][8] f32               (4096)
#define SMEM_BYTES 170528

__device__ __nv_bfloat16 gWpk[16384];   // mix_w: bf16, fragment-packed
__device__ __half        gW2pk[4096];   // w2: fp16, fragment-packed

// ---------------- helpers ----------------
static __device__ __forceinline__ uint32_t s2u(const void* p) {
    uint32_t a;
    asm("{ .reg .u64 t; cvta.to.shared.u64 t, %1; cvt.u32.u64 %0, t; }" : "=r"(a) : "l"(p));
    return a;
}
static __device__ __forceinline__ float gelu_fast(float x) {
    float t = fabsf(x) * 0.7071067811865476f;
    float u = __fdividef(1.0f, fmaf(0.3275911f, t, 1.0f));
    float poly = u * fmaf(u, fmaf(u, fmaf(u, fmaf(u, 1.061405429f, -1.453152027f),
                                          1.421413741f), -0.284496736f), 0.254829592f);
    float e = __expf(-t * t);
    float erfv = fmaf(-poly, e, 1.0f);
    return x * 0.5f * (1.0f + copysignf(erfv, x));
}
static __device__ __forceinline__ float softplus_fast(float x) {
    float e = __expf(-fabsf(x));
    float l = __logf(1.0f + e);
    return x > 0.0f ? x + l : l;
}
static __device__ __forceinline__ void mma16bf(float4& d, uint32_t a0, uint32_t a1,
                                               uint32_t a2, uint32_t a3,
                                               uint32_t b0, uint32_t b1) {
    asm volatile("mma.sync.aligned.m16n8k16.row.col.f32.bf16.bf16.f32 "
                 "{%0,%1,%2,%3}, {%4,%5,%6,%7}, {%8,%9}, {%0,%1,%2,%3};"
                 : "+f"(d.x), "+f"(d.y), "+f"(d.z), "+f"(d.w)
                 : "r"(a0), "r"(a1), "r"(a2), "r"(a3), "r"(b0), "r"(b1));
}
static __device__ __forceinline__ void mma16h(float4& d, uint32_t a0, uint32_t a1,
                                              uint32_t a2, uint32_t a3,
                                              uint32_t b0, uint32_t b1) {
    asm volatile("mma.sync.aligned.m16n8k16.row.col.f32.f16.f16.f32 "
                 "{%0,%1,%2,%3}, {%4,%5,%6,%7}, {%8,%9}, {%0,%1,%2,%3};"
                 : "+f"(d.x), "+f"(d.y), "+f"(d.z), "+f"(d.w)
                 : "r"(a0), "r"(a1), "r"(a2), "r"(a3), "r"(b0), "r"(b1));
}
static __device__ __forceinline__ void ldsm4(uint32_t& r0, uint32_t& r1,
                                             uint32_t& r2, uint32_t& r3, uint32_t addr) {
    asm volatile("ldmatrix.sync.aligned.m8n8.x4.shared.b16 {%0,%1,%2,%3}, [%4];"
                 : "=r"(r0), "=r"(r1), "=r"(r2), "=r"(r3) : "r"(addr));
}

// ---------------- prep kernels ----------------
// mix_w -> gWpk: [nh][ks][ntpair][lid][ntparity][b][h] (validated v7 layout)
__global__ void prep_kernel(const float* __restrict__ mixw) {
    int g = blockIdx.x * 256 + threadIdx.x;
    int i = g >> 11, j = (g >> 8) & 7, k = (g >> 4) & 15, d = g & 15;
    int n  = i * 16 + k;
    int kd = j * 16 + d;
    int nh = n >> 6, nt = (n >> 3) & 7, qt = n & 7;
    int ks = kd >> 4, kr = kd & 15;
    int b  = kr >> 3, qc = (kr & 7) >> 1, h = kr & 1;
    int lid = qt * 4 + qc;
    int idx = nh * 8192 + ks * 1024 + (nt >> 1) * 256 + lid * 8 + (nt & 1) * 4 + b * 2 + h;
    gWpk[idx] = __float2bfloat16(mixw[g]);
}
// w2 -> gW2pk: same fragment geometry, n=64, k=64, fp16
__global__ void prep2_kernel(const float* __restrict__ w2) {
    int g = blockIdx.x * 256 + threadIdx.x;       // 4096
    int o = g >> 6;        // output col (n)
    int i = g & 63;        // k
    int nt = o >> 3, qt = o & 7;
    int ks = i >> 4, kr = i & 15;
    int b  = kr >> 3, qc = (kr & 7) >> 1, h = kr & 1;
    int lid = qt * 4 + qc;
    int idx = ks * 1024 + (nt >> 1) * 256 + lid * 8 + (nt & 1) * 4 + b * 2 + h;
    gW2pk[idx] = __float2half_rn(w2[g]);
}

// ---------------- main fused kernel ----------------
__global__ void __launch_bounds__(THREADS, 1)
soft_equivariant_kernel(const float* __restrict__ z,
                        const float* __restrict__ w1,
                        const float* __restrict__ b1,
                        const float* __restrict__ b2,
                        const float* __restrict__ w3,
                        const float* __restrict__ gb,
                        float* __restrict__ out)
{
    extern __shared__ char smem[];
    float* Zf  = (float*)(smem + ZF_B);
    float* w3t = (float*)(smem + W3T_B);
    float* w1s = (float*)(smem + W1_B);
    float* b1s = (float*)(smem + B1_B);
    float* b2s = (float*)(smem + B2_B);
    float* gts = (float*)(smem + G_B);
    float* scs = (float*)(smem + SC_B);

    const int tid = threadIdx.x;
    const int wid = tid >> 5;
    const int lid = tid & 31;
    const int row0 = blockIdx.x * ROWS;
    const uint32_t smb = s2u(smem);

    // ---- cooperative loads ----
    {
        w1s[tid] = w1[tid];
        { int j = tid >> 6, col = tid & 63; w3t[col * 8 + j] = w3[tid]; }
        if (tid < 64) { b1s[tid] = b1[tid]; b2s[tid] = b2[tid]; }
        if (tid < 8)  gts[tid] = 1.0f / (1.0f + __expf(-gb[tid]));
    }
    {   // packed mixing B: 32KB + packed w2: 8KB linear copies
        const float4* s = (const float4*)gWpk;
        float4* d4 = (float4*)(smem + WH_B);
        #pragma unroll
        for (int e = 0; e < 4; ++e) d4[e * THREADS + tid] = s[e * THREADS + tid];
        const float4* s2 = (const float4*)gW2pk;
        float4* d2 = (float4*)(smem + W2H_B);
        d2[tid] = s2[tid];
    }
    {   // z: fp32 row-major + bf16 copy (272B stride)
        const float4* zg = (const float4*)(z + (size_t)row0 * 128);
        #pragma unroll
        for (int e = 0; e < 8; ++e) {
            int idx = e * THREADS + tid;
            int row = idx >> 5;
            int c4  = idx & 31;
            float4 v = zg[idx];
            *(float4*)(Zf + row * 132 + c4 * 4) = v;
            __nv_bfloat162 p0 = __floats2bfloat162_rn(v.x, v.y);
            __nv_bfloat162 p1 = __floats2bfloat162_rn(v.z, v.w);
            uint2 pr = make_uint2(*(uint32_t*)&p0, *(uint32_t*)&p1);
            *(uint2*)(smem + ZH_B + row * 272 + c4 * 8) = pr;
        }
    }
    __syncthreads();

    if (wid < 8) {
        // ========== GEMM warps: bf16 m16n8k16, 32x64 tile each (v7 verbatim) ===
        const int mw = wid & 3;
        const int nh = wid >> 2;
        const int qt = lid >> 2;
        const int qc = lid & 3;

        float4 acc[2][8];
        #pragma unroll
        for (int mt = 0; mt < 2; ++mt)
            #pragma unroll
            for (int nt = 0; nt < 8; ++nt) acc[mt][nt] = make_float4(0.f, 0.f, 0.f, 0.f);

        const int lm_row = ((lid >> 3) & 1) * 8 + (lid & 7);
        const int lm_col = (lid >> 4) * 16;
        const uint32_t abase = smb + ZH_B + (mw * 32 + lm_row) * 272 + lm_col;
        const char* wbase = smem + WH_B + nh * 16384;

        #pragma unroll
        for (int ks = 0; ks < 8; ++ks) {
            uint32_t a[2][4];
            #pragma unroll
            for (int mt = 0; mt < 2; ++mt)
                ldsm4(a[mt][0], a[mt][1], a[mt][2], a[mt][3],
                      abase + mt * 16 * 272 + ks * 32);
            const char* wp = wbase + ks * 2048 + lid * 16;
            uint4 l0 = *(const uint4*)(wp);
            uint4 l1 = *(const uint4*)(wp + 512);
            uint4 l2 = *(const uint4*)(wp + 1024);
            uint4 l3 = *(const uint4*)(wp + 1536);
            #pragma unroll
            for (int mt = 0; mt < 2; ++mt) {
                mma16bf(acc[mt][0], a[mt][0], a[mt][1], a[mt][2], a[mt][3], l0.x, l0.y);
                mma16bf(acc[mt][1], a[mt][0], a[mt][1], a[mt][2], a[mt][3], l0.z, l0.w);
                mma16bf(acc[mt][2], a[mt][0], a[mt][1], a[mt][2], a[mt][3], l1.x, l1.y);
                mma16bf(acc[mt][3], a[mt][0], a[mt][1], a[mt][2], a[mt][3], l1.z, l1.w);
                mma16bf(acc[mt][4], a[mt][0], a[mt][1], a[mt][2], a[mt][3], l2.x, l2.y);
                mma16bf(acc[mt][5], a[mt][0], a[mt][1], a[mt][2], a[mt][3], l2.z, l2.w);
                mma16bf(acc[mt][6], a[mt][0], a[mt][1], a[mt][2], a[mt][3], l3.x, l3.y);
                mma16bf(acc[mt][7], a[mt][0], a[mt][1], a[mt][2], a[mt][3], l3.z, l3.w);
            }
        }
        __syncthreads();     // wait for MLP warps' scales

        #pragma unroll
        for (int mt = 0; mt < 2; ++mt) {
            #pragma unroll
            for (int nt = 0; nt < 8; ++nt) {
                const int bundle = nh * 4 + (nt >> 1);
                const float g = gts[bundle];
                const int x0 = nh * 64 + nt * 8 + 2 * qc;
                #pragma unroll
                for (int rh = 0; rh < 2; ++rh) {
                    const int r = mw * 32 + mt * 16 + rh * 8 + qt;
                    const float s1 = 1.0f + scs[r * 8 + bundle];
                    float2 zv = *(const float2*)(Zf + r * 132 + x0);
                    float m0 = (rh == 0) ? acc[mt][nt].x : acc[mt][nt].z;
                    float m1 = (rh == 0) ? acc[mt][nt].y : acc[mt][nt].w;
                    float2 o = make_float2(zv.x * s1 + g * m0, zv.y * s1 + g * m1);
                    *(float2*)(out + (size_t)(row0 + r) * 128 + x0) = o;
                }
            }
        }
    } else {
        // ========== MLP warps: each owns 16 rows, fully warp-independent =======
        const int u = wid - 8;            // 0..7
        const int r0 = u * 16;
        const int lrow = lid >> 1;        // 0..15
        const int half = lid & 1;         // k-half / output-half split
        const int row = r0 + lrow;
        const float4* Z4 = (const float4*)Zf;   // 33 float4 per row

        // ---- norms: lane covers 2 of 4 float4 per bundle; pair via shfl_xor(1)
        float pn[8];
        #pragma unroll
        for (int j = 0; j < 8; ++j) pn[j] = 0.0f;
        #pragma unroll
        for (int cc = 0; cc < 2; ++cc) {
            #pragma unroll
            for (int j = 0; j < 8; ++j) {
                float4 v = Z4[row * 33 + j * 4 + 2 * half + cc];
                pn[j] += v.x * v.x + v.y * v.y + v.z * v.z + v.w * v.w;
            }
        }
        float nrm[8];
        #pragma unroll
        for (int j = 0; j < 8; ++j) {
            float o = __shfl_xor_sync(0xffffffffu, pn[j], 1);
            nrm[j] = sqrtf(pn[j] + o) + 1e-8f;
        }

        // ---- layer 1: lane computes 32 outputs (half-split), store fp16 ----
        {
            char* hrow = smem + H1H_B + row * 144 + half * 64;
            #pragma unroll
            for (int q = 0; q < 4; ++q) {        // 8 outputs per q -> one STS.128
                uint32_t pk[4];
                #pragma unroll
                for (int s = 0; s < 4; ++s) {
                    int o = half * 32 + q * 8 + 2 * s;
                    const float4* wr = (const float4*)(w1s + o * 8);
                    float4 wa = wr[0], wb = wr[1];
                    float a0 = b1s[o];
                    a0 += nrm[0] * wa.x + nrm[1] * wa.y + nrm[2] * wa.z + nrm[3] * wa.w;
                    a0 += nrm[4] * wb.x + nrm[5] * wb.y + nrm[6] * wb.z + nrm[7] * wb.w;
                    const float4* wr2 = (const float4*)(w1s + (o + 1) * 8);
                    float4 wc = wr2[0], wd = wr2[1];
                    float a1 = b1s[o + 1];
                    a1 += nrm[0] * wc.x + nrm[1] * wc.y + nrm[2] * wc.z + nrm[3] * wc.w;
                    a1 += nrm[4] * wd.x + nrm[5] * wd.y + nrm[6] * wd.z + nrm[7] * wd.w;
                    __half2 hh = __floats2half2_rn(gelu_fast(a0), gelu_fast(a1));
                    pk[s] = *(uint32_t*)&hh;
                }
                *(uint4*)(hrow + q * 16) = make_uint4(pk[0], pk[1], pk[2], pk[3]);
            }
        }
        __syncwarp();

        // ---- layer 2: fp16 m16n8k16, A = h1[16x64] via ldmatrix, B = packed w2
        const int qt = lid >> 2;
        const int qc = lid & 3;
        float4 acc[8];
        #pragma unroll
        for (int nt = 0; nt < 8; ++nt) acc[nt] = make_float4(0.f, 0.f, 0.f, 0.f);

        {
            const int lm_row = ((lid >> 3) & 1) * 8 + (lid & 7);
            const int lm_col = (lid >> 4) * 16;
            const uint32_t abase = smb + H1H_B + (r0 + lm_row) * 144 + lm_col;
            const char* wbase = smem + W2H_B;
            #pragma unroll
            for (int ks = 0; ks < 4; ++ks) {
                uint32_t a0, a1, a2, a3;
                ldsm4(a0, a1, a2, a3, abase + ks * 32);
                const char* wp = wbase + ks * 2048 + lid * 16;
                uint4 l0 = *(const uint4*)(wp);
                uint4 l1 = *(const uint4*)(wp + 512);
                uint4 l2 = *(const uint4*)(wp + 1024);
                uint4 l3 = *(const uint4*)(wp + 1536);
                mma16h(acc[0], a0, a1, a2, a3, l0.x, l0.y);
                mma16h(acc[1], a0, a1, a2, a3, l0.z, l0.w);
                mma16h(acc[2], a0, a1, a2, a3, l1.x, l1.y);
                mma16h(acc[3], a0, a1, a2, a3, l1.z, l1.w);
                mma16h(acc[4], a0, a1, a2, a3, l2.x, l2.y);
                mma16h(acc[5], a0, a1, a2, a3, l2.z, l2.w);
                mma16h(acc[6], a0, a1, a2, a3, l3.x, l3.y);
                mma16h(acc[7], a0, a1, a2, a3, l3.z, l3.w);
            }
        }

        // ---- bias + gelu on fragments; layer-3 partials; quad reduce ----
        float s0[8], s1[8];
        #pragma unroll
        for (int j = 0; j < 8; ++j) { s0[j] = 0.0f; s1[j] = 0.0f; }
        #pragma unroll
        for (int nt = 0; nt < 8; ++nt) {
            int c0 = nt * 8 + 2 * qc;
            float bb0 = b2s[c0], bb1 = b2s[c0 + 1];
            float h00 = gelu_fast(acc[nt].x + bb0);
            float h01 = gelu_fast(acc[nt].y + bb1);
            float h10 = gelu_fast(acc[nt].z + bb0);
            float h11 = gelu_fast(acc[nt].w + bb1);
            const float4* wa = (const float4*)(w3t + c0 * 8);
            const float4* wb = (const float4*)(w3t + (c0 + 1) * 8);
            float4 wa0 = wa[0], wa1 = wa[1], wb0 = wb[0], wb1 = wb[1];
            s0[0] += h00 * wa0.x + h01 * wb0.x;  s0[1] += h00 * wa0.y + h01 * wb0.y;
            s0[2] += h00 * wa0.z + h01 * wb0.z;  s0[3] += h00 * wa0.w + h01 * wb0.w;
            s0[4] += h00 * wa1.x + h01 * wb1.x;  s0[5] += h00 * wa1.y + h01 * wb1.y;
            s0[6] += h00 * wa1.z + h01 * wb1.z;  s0[7] += h00 * wa1.w + h01 * wb1.w;
            s1[0] += h10 * wa0.x + h11 * wb0.x;  s1[1] += h10 * wa0.y + h11 * wb0.y;
            s1[2] += h10 * wa0.z + h11 * wb0.z;  s1[3] += h10 * wa0.w + h11 * wb0.w;
            s1[4] += h10 * wa1.x + h11 * wb1.x;  s1[5] += h10 * wa1.y + h11 * wb1.y;
            s1[6] += h10 * wa1.z + h11 * wb1.z;  s1[7] += h10 * wa1.w + h11 * wb1.w;
        }
        #pragma unroll
        for (int j = 0; j < 8; ++j) {
            s0[j] += __shfl_xor_sync(0xffffffffu, s0[j], 1);
            s0[j] += __shfl_xor_sync(0xffffffffu, s0[j], 2);
            s1[j] += __shfl_xor_sync(0xffffffffu, s1[j], 1);
            s1[j] += __shfl_xor_sync(0xffffffffu, s1[j], 2);
        }
        if (qc == 0) {
            float* d0 = scs + (r0 + qt) * 8;
            float* d1 = scs + (r0 + qt + 8) * 8;
            *(float4*)(d0)     = make_float4(softplus_fast(s0[0]), softplus_fast(s0[1]),
                                             softplus_fast(s0[2]), softplus_fast(s0[3]));
            *(float4*)(d0 + 4) = make_float4(softplus_fast(s0[4]), softplus_fast(s0[5]),
                                             softplus_fast(s0[6]), softplus_fast(s0[7]));
            *(float4*)(d1)     = make_float4(softplus_fast(s1[0]), softplus_fast(s1[1]),
                                             softplus_fast(s1[2]), softplus_fast(s1[3]));
            *(float4*)(d1 + 4) = make_float4(softplus_fast(s1[4]), softplus_fast(s1[5]),
                                             softplus_fast(s1[6]), softplus_fast(s1[7]));
        }
        __syncthreads();     // release GEMM warps into epilogue
    }
}

extern "C" void kernel_launch(void* const* d_in, const int* in_sizes, int n_in,
                              void* d_out, int out_size)
{
    const float* z    = (const float*)d_in[0];
    const float* w1   = (const float*)d_in[1];
    const float* b1   = (const float*)d_in[2];
    const float* w2   = (const float*)d_in[3];
    const float* b2   = (const float*)d_in[4];
    const float* w3   = (const float*)d_in[5];
    const float* mixw = (const float*)d_in[6];
    const float* gb   = (const float*)d_in[7];
    float* out = (float*)d_out;

    int Btot = in_sizes[0] / 128;            // 524288 rows
    int nblocks = Btot / ROWS;               // 4096

    prep_kernel<<<64, 256>>>(mixw);
    prep2_kernel<<<16, 256>>>(w2);

    static bool attr_set = false;
    if (!attr_set) {
        cudaFuncSetAttribute(soft_equivariant_kernel,
                             cudaFuncAttributeMaxDynamicSharedMemorySize, SMEM_BYTES);
        attr_set = true;
    }
    soft_equivariant_kernel<<<nblocks, THREADS, SMEM_BYTES>>>(
        z, w1, b1, b2, w3, gb, out);
}